// round 10
// baseline (speedup 1.0000x reference)
#include <cuda_runtime.h>
#include <float.h>

// CRF constituency marginals, single-launch inside-outside.
// B=8, S=256, full triu mask (root span = (0,255)).
// One block per batch element (8 blocks x 1024 threads); inter-width
// dependencies resolved with __syncthreads (block owns all its data).
//
// Inside (log space):  A[i,j] = s[i,j] + LSE_{i<k<j}(A[i,k]+A[k,j]),  L = A - s
// Outside (prob space, gather; exponents <= 0, no atomics):
//   mu[p,q] = [root] + sum_{b>q} mu[p,b]*exp(A[p,q]+A[q,b]-L[p,b])
//                    + sum_{a<p} mu[a,q]*exp(A[a,p]+A[p,q]-L[a,q])
//
// All intra-warp reductions use FULL-WARP-UNIFORM loop bounds: every lane of a
// warp executes the same number of iterations (inactive lanes clamp to a valid
// cell and skip the store), so __shfl_xor_sync(0xffffffff,...) is always legal.

constexpr int Bb = 8;
constexpr int Ss = 256;
constexpr int NN = Ss * Ss;
constexpr int NT = 1024;
constexpr int NW = NT / 32;

__device__ float g_A  [Bb * NN];
__device__ float g_AT [Bb * NN];
__device__ float g_L  [Bb * NN];
__device__ float g_LT [Bb * NN];
__device__ float g_mu [Bb * NN];
__device__ float g_muT[Bb * NN];

template<int G> __device__ __forceinline__ float grpMax(float v) {
#pragma unroll
    for (int o = G / 2; o; o >>= 1) v = fmaxf(v, __shfl_xor_sync(0xffffffffu, v, o));
    return v;
}
template<int G> __device__ __forceinline__ float grpSum(float v) {
#pragma unroll
    for (int o = G / 2; o; o >>= 1) v += __shfl_xor_sync(0xffffffffu, v, o);
    return v;
}

// One width of the inside pass. G lanes cooperate per cell, NR terms per lane.
template<int G, int NR>
__device__ __forceinline__ void inside_w(const float* __restrict__ sc,
                                         float* __restrict__ A, float* __restrict__ AT,
                                         float* __restrict__ L, float* __restrict__ LT,
                                         int w, int lane, int warp) {
    const int cells = Ss - w;
    const int sub = lane / G, gl = lane % G;
    const int CPW = 32 / G;
    // Warp-uniform outer bound: all 32 lanes iterate identically.
    for (int c0 = warp * CPW; c0 < cells; c0 += NW * CPW) {
        int c = c0 + sub;
        bool act = (c < cells);
        int i = act ? c : (cells - 1);   // clamp: harmless duplicate work
        int j = i + w;
        const float* Ar  = A  + i * Ss;
        const float* ATr = AT + j * Ss;
        float v[NR], m = -FLT_MAX;
#pragma unroll
        for (int r = 0; r < NR; r++) {
            int k = i + 1 + gl + r * G;
            v[r] = (k < j) ? Ar[k] + ATr[k] : -FLT_MAX;
            m = fmaxf(m, v[r]);
        }
        m = grpMax<G>(m);
        float s = 0.f;
#pragma unroll
        for (int r = 0; r < NR; r++) s += __expf(v[r] - m);  // padded lanes -> 0
        s = grpSum<G>(s);
        if (gl == 0 && act) {
            float lv = m + __logf(s);       // L[i,j] = LSE over splits
            float a  = sc[i * Ss + j] + lv; // A[i,j]
            A [i * Ss + j] = a;  AT[j * Ss + i] = a;
            L [i * Ss + j] = lv; LT[j * Ss + i] = lv;
        }
    }
}

// One width of the outside pass (widths processed 255 -> 1).
template<int G, int NR>
__device__ __forceinline__ void outside_w(float* __restrict__ out,
                                          const float* __restrict__ A,  const float* __restrict__ AT,
                                          const float* __restrict__ L,  const float* __restrict__ LT,
                                          float* __restrict__ mu, float* __restrict__ muT,
                                          int w, int lane, int warp) {
    const int cells = Ss - w;
    const int sub = lane / G, gl = lane % G;
    const int CPW = 32 / G;
    for (int c0 = warp * CPW; c0 < cells; c0 += NW * CPW) {
        int c = c0 + sub;
        bool act = (c < cells);
        int p = act ? c : (cells - 1);
        int q = p + w;
        float apq = A[p * Ss + q];
        int n1 = Ss - 1 - q;   // parents (p,b), b = q+1..255
        int n2 = p;            // parents (a,q), a = 0..p-1
        float acc = 0.f;
#pragma unroll
        for (int r = 0; r < NR; r++) {
            int t = gl + r * G;
            if (t < n1) {
                int b = q + 1 + t;
                acc += mu[p * Ss + b] * __expf(apq + A[q * Ss + b] - L[p * Ss + b]);
            } else if (t - n1 < n2) {
                int a = t - n1;
                acc += muT[q * Ss + a] * __expf(AT[p * Ss + a] + apq - LT[q * Ss + a]);
            }
        }
        acc = grpSum<G>(acc);
        if (gl == 0 && act) {
            if (p == 0 && q == Ss - 1) acc += 1.f;  // root
            mu [p * Ss + q] = acc;
            muT[q * Ss + p] = acc;
            out[p * Ss + q] = acc;
        }
    }
}

#define DISPATCH(FN, nt, ...)                         \
    do {                                              \
        if      ((nt) <= 4)   FN<4, 1>(__VA_ARGS__);  \
        else if ((nt) <= 16)  FN<8, 2>(__VA_ARGS__);  \
        else if ((nt) <= 32)  FN<32, 1>(__VA_ARGS__); \
        else if ((nt) <= 64)  FN<32, 2>(__VA_ARGS__); \
        else if ((nt) <= 128) FN<32, 4>(__VA_ARGS__); \
        else                  FN<32, 8>(__VA_ARGS__); \
    } while (0)

__global__ __launch_bounds__(NT) void crf_kernel(const float* __restrict__ scores,
                                                 float* __restrict__ out) {
    int b = blockIdx.x, tid = threadIdx.x, lane = tid & 31, warp = tid >> 5;
    const float* sc = scores + b * NN;
    float* A  = g_A  + b * NN;  float* AT = g_AT + b * NN;
    float* L  = g_L  + b * NN;  float* LT = g_LT + b * NN;
    float* mu = g_mu + b * NN;  float* muT = g_muT + b * NN;
    float* o  = out + b * NN;

    // zero lower triangle + diagonal of the output
    for (int idx = tid; idx < NN; idx += NT) {
        int i = idx >> 8, j = idx & 255;
        if (j <= i) o[idx] = 0.f;
    }
    // width-1 spans: A = score, L = 0
    for (int c = tid; c < Ss - 1; c += NT) {
        float v = sc[c * Ss + c + 1];
        A [c * Ss + c + 1] = v;   AT[(c + 1) * Ss + c] = v;
        L [c * Ss + c + 1] = 0.f; LT[(c + 1) * Ss + c] = 0.f;
    }
    __syncthreads();

    // inside: widths 2..255
    for (int w = 2; w < Ss; w++) {
        DISPATCH(inside_w, w - 1, sc, A, AT, L, LT, w, lane, warp);
        __syncthreads();
    }
    // outside: widths 255..1 (each mu written before any narrower span reads it)
    for (int w = Ss - 1; w >= 1; w--) {
        DISPATCH(outside_w, Ss - 1 - w, o, A, AT, L, LT, mu, muT, w, lane, warp);
        __syncthreads();
    }
}

extern "C" void kernel_launch(void* const* d_in, const int* in_sizes, int n_in,
                              void* d_out, int out_size) {
    const float* scores = (const float*)d_in[0];
    float* out = (float*)d_out;
    crf_kernel<<<Bb, NT>>>(scores, out);
}

// round 14
// speedup vs baseline: 2.5108x; 2.5108x over previous
#include <cuda_runtime.h>
#include <float.h>

// CRF constituency marginals, single launch, cluster-parallel inside-outside.
// B=8, S=256, full triu mask (root span = (0,255)).
// Grid = 64 CTAs = 8 clusters (one per batch) x 8 CTAs x 1024 threads.
// Inter-width dependency = cluster barrier (~500 cyc) instead of kernel
// launches (~2.5us) or single-SM __syncthreads (8 SMs only).
//
// Inside (log space):  A[i,j] = s[i,j] + LSE_{i<k<j}(A[i,k]+A[k,j]),  L = A - s
// Outside (prob space, gather; exponents <= 0 since L[p,b] >= A[p,q]+A[q,b]):
//   mu[p,q] = [root] + sum_{b>q} mu[p,b]*exp(A[p,q]+A[q,b]-L[p,b])
//                    + sum_{a<p} mu[a,q]*exp(A[a,p]+A[p,q]-L[a,q])
// One warp per cell; strided lane loops (coalesced), full-warp shuffle
// reduction only after loops reconverge. Deterministic, atomic-free.

constexpr int Bb = 8;
constexpr int Ss = 256;
constexpr int NN = Ss * Ss;
constexpr int NT = 1024;      // threads per CTA
constexpr int CPC = 8;        // CTAs per cluster

__device__ float g_A  [Bb * NN];
__device__ float g_AT [Bb * NN];
__device__ float g_L  [Bb * NN];
__device__ float g_LT [Bb * NN];
__device__ float g_mu [Bb * NN];
__device__ float g_muT[Bb * NN];

// barrier.cluster.arrive defaults to .release, .wait to .acquire (cluster
// scope) -> global stores by any CTA in the cluster are visible to all CTAs
// after the barrier (ptxas emits CCTL.IVALL for the L1 invalidate).
__device__ __forceinline__ void cluster_sync() {
    asm volatile("barrier.cluster.arrive.aligned;" ::: "memory");
    asm volatile("barrier.cluster.wait.aligned;" ::: "memory");
}

__device__ __forceinline__ float warpMax(float v) {
#pragma unroll
    for (int o = 16; o; o >>= 1) v = fmaxf(v, __shfl_xor_sync(0xffffffffu, v, o));
    return v;
}
__device__ __forceinline__ float warpSum(float v) {
#pragma unroll
    for (int o = 16; o; o >>= 1) v += __shfl_xor_sync(0xffffffffu, v, o);
    return v;
}

__global__ __cluster_dims__(CPC, 1, 1) __launch_bounds__(NT, 1)
void crf_kernel(const float* __restrict__ scores, float* __restrict__ out) {
    const int b    = blockIdx.x / CPC;
    const int rank = blockIdx.x % CPC;
    const int tid  = threadIdx.x;
    const int lane = tid & 31;
    const int warp = tid >> 5;                 // 0..31

    const float* sc = scores + b * NN;
    float* A   = g_A   + b * NN;  float* AT  = g_AT  + b * NN;
    float* L   = g_L   + b * NN;  float* LT  = g_LT  + b * NN;
    float* mu  = g_mu  + b * NN;  float* muT = g_muT + b * NN;
    float* o   = out   + b * NN;

    // ── init (each CTA does 1/8 of its batch) ──
    for (int idx = rank * NT + tid; idx < NN; idx += CPC * NT) {
        int i = idx >> 8, j = idx & 255;
        if (j <= i) o[idx] = 0.f;
    }
    for (int c = rank * NT + tid; c < Ss - 1; c += CPC * NT) {
        float v = sc[c * Ss + c + 1];
        A [c * Ss + c + 1] = v;   AT[(c + 1) * Ss + c] = v;
        L [c * Ss + c + 1] = 0.f; LT[(c + 1) * Ss + c] = 0.f;
    }
    if (rank == 0 && tid == 0) {               // root marginal = 1
        mu [0 * Ss + (Ss - 1)] = 1.f;
        muT[(Ss - 1) * Ss + 0] = 1.f;
        o  [0 * Ss + (Ss - 1)] = 1.f;
    }
    cluster_sync();

    // ── inside: widths 2..255 ──
    for (int w = 2; w < Ss; w++) {
        const int cells = Ss - w;
        const int cpc   = (cells + CPC - 1) / CPC;     // cells per CTA (<=32)
        const int c     = rank * cpc + warp;
        if (warp < cpc && c < cells && c < (rank + 1) * cpc) {
            const int i = c, j = c + w, n = w - 1;
            const float* Ar = A  + i * Ss + i + 1;     // A[i, i+1+t]
            const float* Br = AT + j * Ss + i + 1;     // A[i+1+t, j]
            float m = -FLT_MAX;
#pragma unroll 4
            for (int t = lane; t < n; t += 32) m = fmaxf(m, Ar[t] + Br[t]);
            m = warpMax(m);
            float s = 0.f;
#pragma unroll 4
            for (int t = lane; t < n; t += 32) s += __expf(Ar[t] + Br[t] - m);
            s = warpSum(s);
            if (lane == 0) {
                float lv = m + __logf(s);              // LSE over splits
                float a  = sc[i * Ss + j] + lv;
                A [i * Ss + j] = a;  AT[j * Ss + i] = a;
                L [i * Ss + j] = lv; LT[j * Ss + i] = lv;
            }
        }
        cluster_sync();
    }

    // ── outside: widths 254..1 (width-255 root set at init) ──
    for (int w = Ss - 2; w >= 1; w--) {
        const int cells = Ss - w;
        const int cpc   = (cells + CPC - 1) / CPC;
        const int c     = rank * cpc + warp;
        if (warp < cpc && c < cells && c < (rank + 1) * cpc) {
            const int p = c, q = c + w;
            const float apq = A[p * Ss + q];
            float acc = 0.f;
            // left-child role: parents (p,b), b = q+1..255
            {
                const int n = Ss - 1 - q;
                const float* M = mu + p * Ss + q + 1;
                const float* X = A  + q * Ss + q + 1;  // A[q,b]
                const float* Y = L  + p * Ss + q + 1;  // L[p,b]
#pragma unroll 4
                for (int t = lane; t < n; t += 32)
                    acc += M[t] * __expf(apq + X[t] - Y[t]);
            }
            // right-child role: parents (a,q), a = 0..p-1
            {
                const int n = p;
                const float* M = muT + q * Ss;         // mu[a,q]
                const float* X = AT  + p * Ss;         // A[a,p]
                const float* Y = LT  + q * Ss;         // L[a,q]
#pragma unroll 4
                for (int t = lane; t < n; t += 32)
                    acc += M[t] * __expf(X[t] + apq - Y[t]);
            }
            acc = warpSum(acc);
            if (lane == 0) {
                mu [p * Ss + q] = acc;
                muT[q * Ss + p] = acc;
                o  [p * Ss + q] = acc;
            }
        }
        cluster_sync();
    }
}

extern "C" void kernel_launch(void* const* d_in, const int* in_sizes, int n_in,
                              void* d_out, int out_size) {
    const float* scores = (const float*)d_in[0];
    float* out = (float*)d_out;
    crf_kernel<<<Bb * CPC, NT>>>(scores, out);
}